// round 16
// baseline (speedup 1.0000x reference)
#include <cuda_runtime.h>
#include <cuda_fp16.h>

#define D       64
#define DV      16          // uint2 (4-half) chunks per row
#define MAX_N   100000
#define MAX_E   1700000
#define NBLK    128         // fully resident (<= SM count)
#define TB      1024
#define XHALF   512         // warps 0..15 : xform (4 tile-units of 128)
#define XS      72          // smem row stride in halves (bank-conflict-free)

// ---------------------------------------------------------------------------
// Device-global scratch. g_cnt zero at load, restored each run (read-clear).
// Barrier counters are monotonic-gen / self-restoring across graph replays.
// ---------------------------------------------------------------------------
__device__ int    g_cnt[MAX_N];
__device__ int    g_off[MAX_N + 1];
__device__ int    g_pos[MAX_N];
__device__ int    g_bsum[NBLK];
__device__ int2   g_edge[MAX_E];
__device__ uint2  g_Yh[MAX_N * DV];    // Y = X @ W^T in fp16

__device__ volatile unsigned g_cbar_gen;  // CSR-half grid barrier
__device__ unsigned          g_cbar_cnt;
__device__ volatile unsigned g_fbar_gen;  // final all-block barrier
__device__ unsigned          g_fbar_cnt;

// Named barriers: 2 = CSR half (512 thr), 3 = xform half (512 thr),
// 4+u = xform tile-unit u (128 thr).
#define CSR_BAR()      asm volatile("bar.sync 2, 512;" ::: "memory")
#define XHALF_BAR()    asm volatile("bar.sync 3, 512;" ::: "memory")
#define XUNIT_BAR(u)   asm volatile("bar.sync %0, 128;" :: "r"(4 + (u)) : "memory")

// Grid barrier among the 128 CSR halves (leader = ct 0). R10-proven pattern.
__device__ __forceinline__ void csr_grid_barrier(int ct) {
    CSR_BAR();
    if (ct == 0) {
        unsigned gen = g_cbar_gen;
        __threadfence();
        unsigned my = atomicAdd(&g_cbar_cnt, 1u);
        if (my == NBLK - 1) {
            g_cbar_cnt = 0;
            __threadfence();
            g_cbar_gen = gen + 1;
        } else {
            while (g_cbar_gen == gen) { }
            __threadfence();
        }
    }
    CSR_BAR();
}

// mma.sync m16n8k16 f16 -> f32 (R13-proven manual fragments)
__device__ __forceinline__ void mma16816(
    float& d0, float& d1, float& d2, float& d3,
    unsigned a0, unsigned a1, unsigned a2, unsigned a3,
    unsigned b0, unsigned b1)
{
    asm volatile(
        "mma.sync.aligned.m16n8k16.row.col.f32.f16.f16.f32 "
        "{%0,%1,%2,%3}, {%4,%5,%6,%7}, {%8,%9}, {%0,%1,%2,%3};"
        : "+f"(d0), "+f"(d1), "+f"(d2), "+f"(d3)
        : "r"(a0), "r"(a1), "r"(a2), "r"(a3), "r"(b0), "r"(b1));
}

// ---------------------------------------------------------------------------
// THE kernel: [xform-half || csr-half] -> full-grid join -> gather phase.
// ---------------------------------------------------------------------------
__global__ __launch_bounds__(TB, 1) void fused_kernel(
    const int*    __restrict__ row,
    const int*    __restrict__ col,
    const float*  __restrict__ vals,
    const float4* __restrict__ X4,     // [N*16]
    const float4* __restrict__ W4,     // [64*16]
    const float4* __restrict__ bias,   // [16]
    float4*       __restrict__ out,    // [N*16]
    int E, int N)
{
    __shared__ __align__(16) __half Wh[64 * XS];          // 9216 B (shared)
    __shared__ __align__(16) __half Xh[4][64 * XS];       // 4 x 9216 B
    __shared__ int s_warp[16];
    __shared__ int s_part[4];
    __shared__ int s_pref;

    const int tid = threadIdx.x;
    const int bid = blockIdx.x;

    if (tid < XHALF) {
        // ===================== xform half (HMMA) =====================
        // Stage W once (512 threads), then unit-local X tiles.
        for (int i = tid; i < 64 * 16; i += XHALF) {
            int r  = i >> 4;
            int cv = i & 15;
            float4 w = __ldg(W4 + i);
            *(__half2*)(Wh + r * XS + cv * 4)     = __floats2half2_rn(w.x, w.y);
            *(__half2*)(Wh + r * XS + cv * 4 + 2) = __floats2half2_rn(w.z, w.w);
        }
        XHALF_BAR();

        const int unit = tid >> 7;        // 0..3
        const int ut   = tid & 127;       // thread in unit
        const int warp = ut >> 5;         // warp in unit (0..3)
        const int lane = ut & 31;
        const int g    = lane >> 2;
        const int c    = (lane & 3) * 2;
        const int m0   = warp * 16;
        __half* Xu = Xh[unit];
        __half* Yh = (__half*)g_Yh;

        const int T = (N + 63) >> 6;      // 1563 tiles of 64 nodes

        for (int t = bid * 4 + unit; t < T; t += NBLK * 4) {
            const int node0 = t << 6;

            // Stage X tile: 1024 float4 / 128 thr = 8 each, batched (MLP=8)
            float4 xr[8];
#pragma unroll
            for (int p = 0; p < 8; p++) {
                int i = p * 128 + ut;
                int n = node0 + (i >> 4);
                xr[p] = (n < N) ? __ldg(X4 + (size_t)n * 16 + (i & 15))
                                : make_float4(0.f, 0.f, 0.f, 0.f);
            }
#pragma unroll
            for (int p = 0; p < 8; p++) {
                int i  = p * 128 + ut;
                int r  = i >> 4;
                int cv = i & 15;
                *(__half2*)(Xu + r * XS + cv * 4)     = __floats2half2_rn(xr[p].x, xr[p].y);
                *(__half2*)(Xu + r * XS + cv * 4 + 2) = __floats2half2_rn(xr[p].z, xr[p].w);
            }
            XUNIT_BAR(unit);

            float acc[8][4];
#pragma unroll
            for (int nt = 0; nt < 8; nt++)
#pragma unroll
                for (int i = 0; i < 4; i++) acc[nt][i] = 0.f;

#pragma unroll
            for (int kt = 0; kt < 4; kt++) {
                const int k0 = kt * 16;
                unsigned a0 = *(const unsigned*)(Xu + (m0 + g)     * XS + k0 + c);
                unsigned a1 = *(const unsigned*)(Xu + (m0 + g + 8) * XS + k0 + c);
                unsigned a2 = *(const unsigned*)(Xu + (m0 + g)     * XS + k0 + c + 8);
                unsigned a3 = *(const unsigned*)(Xu + (m0 + g + 8) * XS + k0 + c + 8);
#pragma unroll
                for (int nt = 0; nt < 8; nt++) {
                    unsigned b0 = *(const unsigned*)(Wh + (nt * 8 + g) * XS + k0 + c);
                    unsigned b1 = *(const unsigned*)(Wh + (nt * 8 + g) * XS + k0 + c + 8);
                    mma16816(acc[nt][0], acc[nt][1], acc[nt][2], acc[nt][3],
                             a0, a1, a2, a3, b0, b1);
                }
            }

            int rA = node0 + m0 + g;
            int rB = rA + 8;
#pragma unroll
            for (int nt = 0; nt < 8; nt++) {
                int colh = nt * 8 + c;
                if (rA < N)
                    *(__half2*)(Yh + (size_t)rA * D + colh) =
                        __floats2half2_rn(acc[nt][0], acc[nt][1]);
                if (rB < N)
                    *(__half2*)(Yh + (size_t)rB * D + colh) =
                        __floats2half2_rn(acc[nt][2], acc[nt][3]);
            }
            XUNIT_BAR(unit);   // before next restage of Xu
        }
    } else {
        // ===================== CSR half (R10-proven) =====================
        const int ct      = tid - XHALF;          // 0..511
        const int gct     = bid * 512 + ct;
        const int cstride = NBLK * 512;           // 65536
        const int nch     = (N + TB - 1) / TB;    // 98 chunks of 1024

        // Phase 1: histogram
        for (int e = gct; e < E; e += cstride)
            atomicAdd(&g_cnt[__ldg(row + e)], 1);
        csr_grid_barrier(ct);

        // Phase 2: per-chunk exclusive scan, 2 elems/thread
        if (bid < nch) {
            int base = bid * TB + ct * 2;
            int a = 0, b = 0;
            if (base < N)     { a = g_cnt[base];     g_cnt[base]     = 0; }
            if (base + 1 < N) { b = g_cnt[base + 1]; g_cnt[base + 1] = 0; }
            int v = a + b;

            int lane = ct & 31;
            int w    = ct >> 5;                   // 0..15
            int s = v;
#pragma unroll
            for (int d = 1; d < 32; d <<= 1) {
                int t = __shfl_up_sync(0xFFFFFFFFu, s, d);
                if (lane >= d) s += t;
            }
            if (lane == 31) s_warp[w] = s;
            CSR_BAR();
            if (w == 0) {
                int ws = (lane < 16) ? s_warp[lane] : 0;
#pragma unroll
                for (int d = 1; d < 16; d <<= 1) {
                    int t = __shfl_up_sync(0xFFFFFFFFu, ws, d);
                    if (lane >= d) ws += t;
                }
                if (lane < 16) s_warp[lane] = ws;
            }
            CSR_BAR();
            int excl = s - v + (w ? s_warp[w - 1] : 0);
            if (base < N)     g_off[base]     = excl;
            if (base + 1 < N) g_off[base + 1] = excl + a;
            if (ct == 511) g_bsum[bid] = excl + v;
        }
        csr_grid_barrier(ct);

        // Phase 3: add chunk prefix, init cursors
        if (bid < nch) {
            if (ct < 128) {
                int vp = (ct < bid) ? g_bsum[ct] : 0;
#pragma unroll
                for (int d = 16; d >= 1; d >>= 1)
                    vp += __shfl_down_sync(0xFFFFFFFFu, vp, d);
                if ((ct & 31) == 0) s_part[ct >> 5] = vp;
            }
            CSR_BAR();
            if (ct == 0)
                s_pref = s_part[0] + s_part[1] + s_part[2] + s_part[3];
            CSR_BAR();
            int pref = s_pref;
            int base = bid * TB + ct * 2;
            if (base < N) {
                int o = g_off[base] + pref;
                g_off[base] = o; g_pos[base] = o;
            }
            if (base + 1 < N) {
                int o = g_off[base + 1] + pref;
                g_off[base + 1] = o; g_pos[base + 1] = o;
            }
        }
        if (bid == 0 && ct == 0) g_off[N] = E;
        csr_grid_barrier(ct);

        // Phase 4: bin edges (batch 4 for MLP)
        {
            int e = gct;
            for (; e + 3 * cstride < E; e += 4 * cstride) {
                int e1 = e + cstride, e2 = e + 2 * cstride, e3 = e + 3 * cstride;
                int   r0 = __ldg(row + e),  r1 = __ldg(row + e1);
                int   r2 = __ldg(row + e2), r3 = __ldg(row + e3);
                int   c0 = __ldg(col + e),  c1 = __ldg(col + e1);
                int   c2 = __ldg(col + e2), c3 = __ldg(col + e3);
                float v0 = __ldg(vals + e),  v1 = __ldg(vals + e1);
                float v2 = __ldg(vals + e2), v3 = __ldg(vals + e3);
                int p0 = atomicAdd(&g_pos[r0], 1);
                int p1 = atomicAdd(&g_pos[r1], 1);
                int p2 = atomicAdd(&g_pos[r2], 1);
                int p3 = atomicAdd(&g_pos[r3], 1);
                g_edge[p0] = make_int2(c0, __float_as_int(v0));
                g_edge[p1] = make_int2(c1, __float_as_int(v1));
                g_edge[p2] = make_int2(c2, __float_as_int(v2));
                g_edge[p3] = make_int2(c3, __float_as_int(v3));
            }
            for (; e < E; e += cstride) {
                int r = __ldg(row + e);
                int p = atomicAdd(&g_pos[r], 1);
                g_edge[p] = make_int2(__ldg(col + e),
                                      __float_as_int(__ldg(vals + e)));
            }
        }
    }

    // =================== full-grid join (R8-proven pattern) ===================
    __threadfence();
    __syncthreads();
    if (tid == 0) {
        unsigned gen = g_fbar_gen;
        __threadfence();
        unsigned my = atomicAdd(&g_fbar_cnt, 1u);
        if (my == NBLK - 1) {
            g_fbar_cnt = 0;
            __threadfence();
            g_fbar_gen = gen + 1;
        } else {
            while (g_fbar_gen == gen) { }
            __threadfence();
        }
    }
    __syncthreads();

    // =================== gather phase (R11-proven body) ===================
    {
        const int q = tid & 15;               // constant across iterations
        float4 bq = __ldg(bias + q);
        const int total  = N * DV;
        const int stride = NBLK * TB;         // 131072

        for (int idx = bid * TB + tid; idx < total; idx += stride) {
            int n = idx >> 4;
            int s = __ldg(&g_off[n]);
            int e = __ldg(&g_off[n + 1]);

            float4 acc = bq;
            int j = s;

            for (; j + 8 <= e; j += 8) {
                int2 p[8];
#pragma unroll
                for (int u = 0; u < 8; u++) p[u] = g_edge[j + u];
                uint2 y[8];
#pragma unroll
                for (int u = 0; u < 8; u++)
                    y[u] = __ldg(&g_Yh[(size_t)p[u].x * DV + q]);
#pragma unroll
                for (int u = 0; u < 8; u++) {
                    float v = __int_as_float(p[u].y);
                    __half2 h01 = *reinterpret_cast<__half2*>(&y[u].x);
                    __half2 h23 = *reinterpret_cast<__half2*>(&y[u].y);
                    float2 f01 = __half22float2(h01);
                    float2 f23 = __half22float2(h23);
                    acc.x += v * f01.x; acc.y += v * f01.y;
                    acc.z += v * f23.x; acc.w += v * f23.y;
                }
            }
            for (; j + 4 <= e; j += 4) {
                int2 p[4];
#pragma unroll
                for (int u = 0; u < 4; u++) p[u] = g_edge[j + u];
                uint2 y[4];
#pragma unroll
                for (int u = 0; u < 4; u++)
                    y[u] = __ldg(&g_Yh[(size_t)p[u].x * DV + q]);
#pragma unroll
                for (int u = 0; u < 4; u++) {
                    float v = __int_as_float(p[u].y);
                    __half2 h01 = *reinterpret_cast<__half2*>(&y[u].x);
                    __half2 h23 = *reinterpret_cast<__half2*>(&y[u].y);
                    float2 f01 = __half22float2(h01);
                    float2 f23 = __half22float2(h23);
                    acc.x += v * f01.x; acc.y += v * f01.y;
                    acc.z += v * f23.x; acc.w += v * f23.y;
                }
            }
            for (; j < e; j++) {
                int2 p = g_edge[j];
                uint2 y = __ldg(&g_Yh[(size_t)p.x * DV + q]);
                float v = __int_as_float(p.y);
                __half2 h01 = *reinterpret_cast<__half2*>(&y.x);
                __half2 h23 = *reinterpret_cast<__half2*>(&y.y);
                float2 f01 = __half22float2(h01);
                float2 f23 = __half22float2(h23);
                acc.x += v * f01.x; acc.y += v * f01.y;
                acc.z += v * f23.x; acc.w += v * f23.y;
            }
            out[idx] = acc;
        }
    }
}

// ---------------------------------------------------------------------------
// Launch: inputs in metadata order: row, col, vals, X, weight, bias
// ONE graph node.
// ---------------------------------------------------------------------------
extern "C" void kernel_launch(void* const* d_in, const int* in_sizes, int n_in,
                              void* d_out, int out_size)
{
    const int*   row  = (const int*)  d_in[0];
    const int*   col  = (const int*)  d_in[1];
    const float* vals = (const float*)d_in[2];
    const float* X    = (const float*)d_in[3];
    const float* W    = (const float*)d_in[4];
    const float* bias = (const float*)d_in[5];
    float*       out  = (float*)d_out;

    int E = in_sizes[0];
    int N = in_sizes[3] / D;   // 100000

    fused_kernel<<<NBLK, TB>>>(
        row, col, vals,
        (const float4*)X, (const float4*)W, (const float4*)bias,
        (float4*)out, E, N);
}